// round 13
// baseline (speedup 1.0000x reference)
#include <cuda_runtime.h>
#include <cuda_bf16.h>
#include <cstdint>

#define HW 16384
#define OFF_PI 0
#define OFF_MU 2097152
#define OFF_SIG 35651584
#define OFF_G 37748736

#define KPAD 168  // B tile K stride (channels); 152 real + zero pad

// smem byte offsets (total 112512 -> 2 CTAs/SM)
#define SMB_B 0         // Bh 43008 | Bl 43008 ; reused as mn tile post-GEMM
#define SMB_SLH 86016   // A-slice hi bf16 [128 px][16 ch] = 4096
#define SMB_SLL 90112   // A-slice lo bf16                 = 4096
#define SMB_X 94208     // x fp32 [16][128]                = 8192
#define SMB_AL 102400   // dist accum -> alpha [8][128]    = 4096
#define SMB_S 106496    // Wsig^T fp32 [152][8]            = 4864
#define SMB_BMU 111360  // 128 f
#define SMB_WPI 111872  // 128 f
#define SMB_MISC 112384 // bpi[0..7] bsig[8..15] Wg[16..23] bg[24]
#define SMEM_BYTES 112512

#define MN_STRIDE 132      // fp32 mu_new tile [128 out][132], in SMB_B
#define SMB_SPARE 67584    // sj/d2 partials [128 px][16 f], in SMB_B region

typedef unsigned long long ull;

// Precomputed Wmu bf16 hi/lo tiles, [128][KPAD] row-major, contiguous.
__device__ __align__(16) __nv_bfloat16 g_B[2][128 * KPAD];

extern "C" __global__ void prep_B_kernel(const float* __restrict__ Wmu) {
    int i = blockIdx.x * 256 + threadIdx.x;
    if (i >= 128 * KPAD) return;
    int o = i / KPAD, c = i - o * KPAD;
    float v = (c < 152) ? Wmu[o * 152 + c] : 0.f;
    __nv_bfloat16 hi = __float2bfloat16(v);
    __nv_bfloat16 lo = __float2bfloat16(v - __bfloat162float(hi));
    g_B[0][i] = hi;
    g_B[1][i] = lo;
}

__device__ __forceinline__ void hmma_bf16(float* d, uint32_t a0, uint32_t a1,
                                          uint32_t a2, uint32_t a3,
                                          uint32_t b0, uint32_t b1) {
    asm volatile(
        "mma.sync.aligned.m16n8k16.row.col.f32.bf16.bf16.f32 "
        "{%0,%1,%2,%3}, {%4,%5,%6,%7}, {%8,%9}, {%0,%1,%2,%3};"
        : "+f"(d[0]), "+f"(d[1]), "+f"(d[2]), "+f"(d[3])
        : "r"(a0), "r"(a1), "r"(a2), "r"(a3), "r"(b0), "r"(b1));
}

// pack 8 consecutive-channel fp32 -> 4 bf16x2 hi words + 4 lo words
__device__ __forceinline__ void pack8(const float* v, uint4& hi, uint4& lo) {
    uint32_t h[4], l[4];
#pragma unroll
    for (int i = 0; i < 4; i++) {
        float a = v[2 * i], c = v[2 * i + 1];
        __nv_bfloat162 h2 = __floats2bfloat162_rn(a, c);
        float2 hf = __bfloat1622float2(h2);
        __nv_bfloat162 l2 = __floats2bfloat162_rn(a - hf.x, c - hf.y);
        h[i] = *(uint32_t*)&h2;
        l[i] = *(uint32_t*)&l2;
    }
    hi = make_uint4(h[0], h[1], h[2], h[3]);
    lo = make_uint4(l[0], l[1], l[2], l[3]);
}

extern "C" __global__ void __launch_bounds__(256, 2)
gmm_block_kernel(const float* __restrict__ x, const float* __restrict__ pi_in,
                 const float* __restrict__ mu, const float* __restrict__ sigma,
                 const float* __restrict__ Wpi, const float* __restrict__ bpi,
                 const float* __restrict__ Wmu, const float* __restrict__ bmu,
                 const float* __restrict__ Wsig, const float* __restrict__ bsig,
                 const float* __restrict__ Wg, const float* __restrict__ bg,
                 float* __restrict__ out) {
    extern __shared__ char sm[];
    float* shX = (float*)(sm + SMB_X);
    float* shAL = (float*)(sm + SMB_AL);
    float* shS = (float*)(sm + SMB_S);
    float* shBMU = (float*)(sm + SMB_BMU);
    float* shWPI = (float*)(sm + SMB_WPI);
    float* shMISC = (float*)(sm + SMB_MISC);
    uint32_t* SLH32 = (uint32_t*)(sm + SMB_SLH);
    uint32_t* SLL32 = (uint32_t*)(sm + SMB_SLL);
    uint32_t* BH32 = (uint32_t*)(sm + SMB_B);
    uint32_t* BL32 = (uint32_t*)(sm + SMB_B + 43008);
    float* mn = (float*)(sm + SMB_B);             // after GEMM (B dead)
    float* spare = (float*)(sm + SMB_B + SMB_SPARE);

    const int tid = threadIdx.x;
    const int blk = blockIdx.x;  // 2048 CTAs x 128 pixels
    const int b = blk >> 7;
    const int hw0 = (blk & 127) << 7;

    // ---- stage 1: cp.async B (86KB, L2-hot) + stage small operands --------
    {
        uint32_t dst = (uint32_t)__cvta_generic_to_shared(sm + SMB_B);
        const char* src = (const char*)&g_B[0][0];
#pragma unroll 1
        for (int i = tid * 16; i < 86016; i += 256 * 16) {
            asm volatile("cp.async.cg.shared.global [%0], [%1], 16;" ::"r"(
                             dst + i),
                         "l"(src + i)
                         : "memory");
        }
        asm volatile("cp.async.commit_group;" ::: "memory");
    }
    for (int i = tid; i < 1216; i += 256) {  // Wsig[j][c] -> shS[c][j]
        int j = i / 152, c = i - j * 152;
        shS[c * 8 + j] = Wsig[i];
    }
    for (int i = tid; i < 2048; i += 256) {
        int c = i >> 7, p = i & 127;
        shX[i] = x[(b * 16 + c) * HW + hw0 + p];
    }
    if (tid < 128) {
        shBMU[tid] = bmu[tid];
        shWPI[tid] = Wpi[tid];
    } else if (tid < 136) {
        int k = tid - 128;
        shMISC[k] = bpi[k];
        shMISC[8 + k] = bsig[k];
        shMISC[16 + k] = Wg[k];
    }
    if (tid == 255) shMISC[24] = bg[0];
    for (int i = tid; i < 1024; i += 256) shAL[i] = 0.f;  // dist accum
    __syncthreads();  // shX staged (cp.async for B still in flight)

    const int w = tid >> 5, l = tid & 31;
    const int g = l >> 2, t = l & 3;
    const int m0 = 16 * w;
    const int p = tid & 127, h = tid >> 7;  // slice-builder role

    // ---- build slice 0 (x channels) while B streams in ---------------------
    {
        float v0[8];
#pragma unroll
        for (int j = 0; j < 8; j++) v0[j] = shX[(8 * h + j) * 128 + p];
        uint4 hi, lo;
        pack8(v0, hi, lo);
        *(uint4*)((char*)SLH32 + p * 32 + h * 16) = hi;
        *(uint4*)((char*)SLL32 + p * 32 + h * 16) = lo;
    }
    asm volatile("cp.async.wait_group 0;" ::: "memory");
    __syncthreads();  // slice 0 + B visible

    float acc[16][4];
#pragma unroll
    for (int n = 0; n < 16; n++)
#pragma unroll
        for (int q = 0; q < 4; q++) acc[n][q] = 0.f;

    // ---- fused slice-streamed GEMM with register prefetch ------------------
#pragma unroll 1
    for (int c = 0; c < 10; c++) {
        // prefetch mu for chunk c+1 (components 0..7 -> chunks 1..8)
        float v[8];
        if (c < 8) {
            const float* mk = mu + (b * 128 + c * 16 + 8 * h) * HW + hw0 + p;
#pragma unroll
            for (int j = 0; j < 8; j++) v[j] = mk[j * HW];
        }

        // consume slice c: 48 HMMA, 3 bf16-split passes merged per n
        {
            const int ar0 = (m0 + g) * 8 + t;
            const int ar1 = (m0 + g + 8) * 8 + t;
            uint32_t ah0 = SLH32[ar0], ah1 = SLH32[ar1];
            uint32_t ah2 = SLH32[ar0 + 4], ah3 = SLH32[ar1 + 4];
            uint32_t al0 = SLL32[ar0], al1 = SLL32[ar1];
            uint32_t al2 = SLL32[ar0 + 4], al3 = SLL32[ar1 + 4];
#pragma unroll
            for (int n = 0; n < 16; n++) {
                const int br = (8 * n + g) * 84 + 8 * c + t;
                uint32_t bh0 = BH32[br], bh1 = BH32[br + 4];
                uint32_t bl0 = BL32[br], bl1 = BL32[br + 4];
                hmma_bf16(acc[n], ah0, ah1, ah2, ah3, bh0, bh1);
                hmma_bf16(acc[n], ah0, ah1, ah2, ah3, bl0, bl1);
                hmma_bf16(acc[n], al0, al1, al2, al3, bh0, bh1);
            }
        }
        if (c == 9) break;
        __syncthreads();  // all reads of slice done

        // pack chunk c+1
        if (c < 8) {
            float dk = 0.f;
#pragma unroll
            for (int j = 0; j < 8; j++) {
                float d = shX[(8 * h + j) * 128 + p] - v[j];
                dk = fmaf(d, d, dk);
            }
            atomicAdd(&shAL[c * 128 + p], dk);  // 2 adds: fp-commutative
            uint4 hi, lo;
            pack8(v, hi, lo);
            *(uint4*)((char*)SLH32 + p * 32 + h * 16) = hi;
            *(uint4*)((char*)SLL32 + p * 32 + h * 16) = lo;
        } else {
            // c == 8: finalize dens/alpha/rho, build rho slice (chunk 9)
            if (h == 0) {
                float rho[8];
#pragma unroll
                for (int k = 0; k < 8; k++) {
                    float dist = shAL[k * 128 + p];
                    float sg = sigma[(b * 8 + k) * HW + hw0 + p];
                    float pv = pi_in[(b * 8 + k) * HW + hw0 + p];
                    float s2 = sg * sg;
                    float tt = 6.283185307179586f * s2;
                    float t2 = tt * tt, t4 = t2 * t2;
                    float dens = __expf(-dist / (2.f * s2)) / (t4 * t4);
                    float a = pv * dens;
                    shAL[k * 128 + p] = a;  // alpha overwrites dist
                    rho[k] = a * dens;
                }
                uint4 hi, lo;
                pack8(rho, hi, lo);
                *(uint4*)((char*)SLH32 + p * 32) = hi;
                *(uint4*)((char*)SLL32 + p * 32) = lo;
            } else {
                *(uint4*)((char*)SLH32 + p * 32 + 16) = make_uint4(0, 0, 0, 0);
                *(uint4*)((char*)SLL32 + p * 32 + 16) = make_uint4(0, 0, 0, 0);
            }
        }
        __syncthreads();  // slice c+1 ready
    }
    __syncthreads();  // all B reads done before mn overwrite

    // ---- scatter acc -> mn tile (B region dead) ---------------------------
#pragma unroll
    for (int n = 0; n < 16; n++) {
        const int nc = 8 * n + 2 * t;
        mn[nc * MN_STRIDE + m0 + g] = acc[n][0];
        mn[(nc + 1) * MN_STRIDE + m0 + g] = acc[n][1];
        mn[nc * MN_STRIDE + m0 + g + 8] = acc[n][2];
        mn[(nc + 1) * MN_STRIDE + m0 + g + 8] = acc[n][3];
    }
    __syncthreads();

    // ---- finalize: 256 threads, warp-pairs split the 128 outputs ----------
    {
        const int hh = w >> 2;                   // output half
        const int pp = ((w & 3) << 5) | l;       // pixel 0..127
        const int ob = hh * 64;

        float sj[8];
#pragma unroll
        for (int j = 0; j < 8; j++) sj[j] = hh ? 0.f : shMISC[8 + j];
        float d2l[4] = {0.f, 0.f, 0.f, 0.f};
        float* outMuBase = out + OFF_MU + (b * 128 + ob) * HW + hw0 + pp;
#pragma unroll 4
        for (int oo = 0; oo < 64; oo++) {
            const int o = ob + oo;
            float v = mn[o * MN_STRIDE + pp] + shBMU[o];
            v = fmaxf(v, 0.f);
            outMuBase[oo * HW] = v;
            float4 wsa = *(const float4*)(shS + (16 + o) * 8);
            float4 wsb = *(const float4*)(shS + (16 + o) * 8 + 4);
            sj[0] = fmaf(wsa.x, v, sj[0]);
            sj[1] = fmaf(wsa.y, v, sj[1]);
            sj[2] = fmaf(wsa.z, v, sj[2]);
            sj[3] = fmaf(wsa.w, v, sj[3]);
            sj[4] = fmaf(wsb.x, v, sj[4]);
            sj[5] = fmaf(wsb.y, v, sj[5]);
            sj[6] = fmaf(wsb.z, v, sj[6]);
            sj[7] = fmaf(wsb.w, v, sj[7]);
            float d = shX[(o & 15) * 128 + pp] - v;
            d2l[oo >> 4] = fmaf(d, d, d2l[oo >> 4]);
        }
        if (hh) {
#pragma unroll
            for (int j = 0; j < 8; j++) spare[pp * 16 + j] = sj[j];
#pragma unroll
            for (int i = 0; i < 4; i++) spare[pp * 16 + 8 + i] = d2l[i];
        }
        __syncthreads();
        if (!hh) {
            float d2[8];
#pragma unroll
            for (int j = 0; j < 8; j++) sj[j] += spare[pp * 16 + j];
#pragma unroll
            for (int i = 0; i < 4; i++) {
                d2[i] = d2l[i];
                d2[4 + i] = spare[pp * 16 + 8 + i];
            }
            // rho from chunk-9 slice (hi+lo bf16)
            float rho[8];
            {
                const __nv_bfloat16* rh =
                    (const __nv_bfloat16*)((char*)SLH32 + pp * 32);
                const __nv_bfloat16* rl =
                    (const __nv_bfloat16*)((char*)SLL32 + pp * 32);
#pragma unroll
                for (int r = 0; r < 8; r++)
                    rho[r] = __bfloat162float(rh[r]) + __bfloat162float(rl[r]);
            }
            // softmax -> pi_new
            float piv[8], al[8], z[8], pin[8];
#pragma unroll
            for (int k = 0; k < 8; k++) {
                piv[k] = pi_in[(b * 8 + k) * HW + hw0 + pp];
                al[k] = shAL[k * 128 + pp];
            }
            float zmax = -1e30f;
#pragma unroll
            for (int j = 0; j < 8; j++) {
                float zj = shMISC[j];
#pragma unroll
                for (int i = 0; i < 8; i++) {
                    zj = fmaf(shWPI[j * 16 + i], piv[i], zj);
                    zj = fmaf(shWPI[j * 16 + 8 + i], al[i], zj);
                }
                z[j] = zj;
                zmax = fmaxf(zmax, zj);
            }
            float s = 0.f;
#pragma unroll
            for (int j = 0; j < 8; j++) {
                z[j] = __expf(z[j] - zmax);
                s += z[j];
            }
            float inv = 1.0f / s;
#pragma unroll
            for (int j = 0; j < 8; j++) {
                pin[j] = z[j] * inv;
                out[OFF_PI + (b * 8 + j) * HW + hw0 + pp] = pin[j];
            }
            // x and rho channels of sigma matvec
#pragma unroll 4
            for (int c = 0; c < 16; c++) {
                float xv = shX[c * 128 + pp];
#pragma unroll
                for (int j = 0; j < 8; j++)
                    sj[j] = fmaf(shS[c * 8 + j], xv, sj[j]);
            }
#pragma unroll
            for (int r = 0; r < 8; r++) {
#pragma unroll
                for (int j = 0; j < 8; j++)
                    sj[j] = fmaf(shS[(144 + r) * 8 + j], rho[r], sj[j]);
            }
            float gg = shMISC[24];
#pragma unroll
            for (int j = 0; j < 8; j++) {
                float sn = __expf(fmaxf(sj[j], 0.f));
                out[OFF_SIG + (b * 8 + j) * HW + hw0 + pp] = sn;
                float s2 = sn * sn;
                float tt = 6.283185307179586f * s2;
                float t2 = tt * tt, t4 = t2 * t2;
                float dens2 = __expf(-d2[j] / (2.f * s2)) / (t4 * t4);
                gg = fmaf(shMISC[16 + j], pin[j] * dens2, gg);
            }
            out[OFF_G + b * HW + hw0 + pp] = 1.0f / (1.0f + __expf(-gg));
        }
    }
}

extern "C" void kernel_launch(void* const* d_in, const int* in_sizes, int n_in,
                              void* d_out, int out_size) {
    (void)in_sizes;
    (void)n_in;
    (void)out_size;
    const float* x = (const float*)d_in[0];
    const float* pi = (const float*)d_in[1];
    const float* mu = (const float*)d_in[2];
    const float* sigma = (const float*)d_in[3];
    const float* Wpi = (const float*)d_in[4];
    const float* bpi = (const float*)d_in[5];
    const float* Wmu = (const float*)d_in[6];
    const float* bmu = (const float*)d_in[7];
    const float* Wsig = (const float*)d_in[8];
    const float* bsig = (const float*)d_in[9];
    const float* Wg = (const float*)d_in[10];
    const float* bg = (const float*)d_in[11];
    float* out = (float*)d_out;

    prep_B_kernel<<<(128 * KPAD + 255) / 256, 256>>>(Wmu);

    cudaFuncSetAttribute(gmm_block_kernel,
                         cudaFuncAttributeMaxDynamicSharedMemorySize,
                         SMEM_BYTES);
    gmm_block_kernel<<<2048, 256, SMEM_BYTES>>>(x, pi, mu, sigma, Wpi, bpi,
                                                Wmu, bmu, Wsig, bsig, Wg, bg,
                                                out);
}

// round 14
// speedup vs baseline: 1.3266x; 1.3266x over previous
#include <cuda_runtime.h>
#include <cuda_bf16.h>
#include <cstdint>

#define HW 16384
#define OFF_PI 0
#define OFF_MU 2097152
#define OFF_SIG 35651584
#define OFF_G 37748736

#define KPAD 168  // B tile K stride (channels); 152 real + zero pad

// smem byte offsets (total 112512 -> 2 CTAs/SM)
#define SMB_B 0         // Bh 43008 | Bl 43008 ; reused as mn tile post-GEMM
#define SMB_SLH 86016   // A-slice hi bf16 [128 px][16 ch] = 4096
#define SMB_SLL 90112   // A-slice lo bf16                 = 4096
#define SMB_X 94208     // x fp32 [16][128]                = 8192
#define SMB_AL 102400   // dist accum -> alpha [8][128]    = 4096
#define SMB_S 106496    // Wsig^T fp32 [152][8]            = 4864
#define SMB_BMU 111360  // 128 f
#define SMB_WPI 111872  // 128 f
#define SMB_MISC 112384 // bpi[0..7] bsig[8..15] Wg[16..23] bg[24]
#define SMEM_BYTES 112512

#define MN_STRIDE 132      // fp32 mu_new tile [128 out][132], in SMB_B
#define SMB_SPARE 67584    // sj/d2 partials [128 px][16 f], in SMB_B region

typedef unsigned long long ull;

// Precomputed Wmu bf16 hi/lo tiles, [128][KPAD] row-major, contiguous.
__device__ __align__(16) __nv_bfloat16 g_B[2][128 * KPAD];

extern "C" __global__ void prep_B_kernel(const float* __restrict__ Wmu) {
    int i = blockIdx.x * 256 + threadIdx.x;
    if (i >= 128 * KPAD) return;
    int o = i / KPAD, c = i - o * KPAD;
    float v = (c < 152) ? Wmu[o * 152 + c] : 0.f;
    __nv_bfloat16 hi = __float2bfloat16(v);
    __nv_bfloat16 lo = __float2bfloat16(v - __bfloat162float(hi));
    g_B[0][i] = hi;
    g_B[1][i] = lo;
}

__device__ __forceinline__ void hmma_bf16(float* d, uint32_t a0, uint32_t a1,
                                          uint32_t a2, uint32_t a3,
                                          uint32_t b0, uint32_t b1) {
    asm volatile(
        "mma.sync.aligned.m16n8k16.row.col.f32.bf16.bf16.f32 "
        "{%0,%1,%2,%3}, {%4,%5,%6,%7}, {%8,%9}, {%0,%1,%2,%3};"
        : "+f"(d[0]), "+f"(d[1]), "+f"(d[2]), "+f"(d[3])
        : "r"(a0), "r"(a1), "r"(a2), "r"(a3), "r"(b0), "r"(b1));
}

// pack 8 consecutive-channel fp32 -> 4 bf16x2 hi words + 4 lo words
__device__ __forceinline__ void pack8(const float* v, uint4& hi, uint4& lo) {
    uint32_t h[4], l[4];
#pragma unroll
    for (int i = 0; i < 4; i++) {
        float a = v[2 * i], c = v[2 * i + 1];
        __nv_bfloat162 h2 = __floats2bfloat162_rn(a, c);
        float2 hf = __bfloat1622float2(h2);
        __nv_bfloat162 l2 = __floats2bfloat162_rn(a - hf.x, c - hf.y);
        h[i] = *(uint32_t*)&h2;
        l[i] = *(uint32_t*)&l2;
    }
    hi = make_uint4(h[0], h[1], h[2], h[3]);
    lo = make_uint4(l[0], l[1], l[2], l[3]);
}

extern "C" __global__ void __launch_bounds__(256, 2)
gmm_block_kernel(const float* __restrict__ x, const float* __restrict__ pi_in,
                 const float* __restrict__ mu, const float* __restrict__ sigma,
                 const float* __restrict__ Wpi, const float* __restrict__ bpi,
                 const float* __restrict__ Wmu, const float* __restrict__ bmu,
                 const float* __restrict__ Wsig, const float* __restrict__ bsig,
                 const float* __restrict__ Wg, const float* __restrict__ bg,
                 float* __restrict__ out) {
    extern __shared__ char sm[];
    float* shX = (float*)(sm + SMB_X);
    float* shAL = (float*)(sm + SMB_AL);
    float* shS = (float*)(sm + SMB_S);
    float* shBMU = (float*)(sm + SMB_BMU);
    float* shWPI = (float*)(sm + SMB_WPI);
    float* shMISC = (float*)(sm + SMB_MISC);
    uint32_t* SLH32 = (uint32_t*)(sm + SMB_SLH);
    uint32_t* SLL32 = (uint32_t*)(sm + SMB_SLL);
    uint32_t* BH32 = (uint32_t*)(sm + SMB_B);
    uint32_t* BL32 = (uint32_t*)(sm + SMB_B + 43008);
    float* mn = (float*)(sm + SMB_B);             // after GEMM (B dead)
    float* spare = (float*)(sm + SMB_B + SMB_SPARE);

    const int tid = threadIdx.x;
    const int blk = blockIdx.x;  // 2048 CTAs x 128 pixels
    const int b = blk >> 7;
    const int hw0 = (blk & 127) << 7;

    // ---- stage 1: cp.async B (86KB, L2-hot) + stage small operands --------
    {
        uint32_t dst = (uint32_t)__cvta_generic_to_shared(sm + SMB_B);
        const char* src = (const char*)&g_B[0][0];
#pragma unroll 1
        for (int i = tid * 16; i < 86016; i += 256 * 16) {
            asm volatile("cp.async.cg.shared.global [%0], [%1], 16;" ::"r"(
                             dst + i),
                         "l"(src + i)
                         : "memory");
        }
        asm volatile("cp.async.commit_group;" ::: "memory");
    }
    for (int i = tid; i < 1216; i += 256) {  // Wsig[j][c] -> shS[c][j]
        int j = i / 152, c = i - j * 152;
        shS[c * 8 + j] = Wsig[i];
    }
    for (int i = tid; i < 2048; i += 256) {
        int c = i >> 7, p = i & 127;
        shX[i] = x[(b * 16 + c) * HW + hw0 + p];
    }
    if (tid < 128) {
        shBMU[tid] = bmu[tid];
        shWPI[tid] = Wpi[tid];
    } else if (tid < 136) {
        int k = tid - 128;
        shMISC[k] = bpi[k];
        shMISC[8 + k] = bsig[k];
        shMISC[16 + k] = Wg[k];
    }
    if (tid == 255) shMISC[24] = bg[0];
    for (int i = tid; i < 1024; i += 256) shAL[i] = 0.f;  // dist accum
    __syncthreads();  // shX staged (cp.async for B still in flight)

    const int w = tid >> 5, l = tid & 31;
    const int g = l >> 2, t = l & 3;
    const int m0 = 16 * w;
    const int p = tid & 127, h = tid >> 7;  // slice-builder role

    // ---- build slice 0 (x channels) while B streams in --------------------
    {
        float v0[8];
#pragma unroll
        for (int j = 0; j < 8; j++) v0[j] = shX[(8 * h + j) * 128 + p];
        uint4 hi, lo;
        pack8(v0, hi, lo);
        *(uint4*)((char*)SLH32 + p * 32 + h * 16) = hi;
        *(uint4*)((char*)SLL32 + p * 32 + h * 16) = lo;
    }
    asm volatile("cp.async.wait_group 0;" ::: "memory");
    __syncthreads();  // slice 0 + B visible

    float acc[16][4];
#pragma unroll
    for (int n = 0; n < 16; n++)
#pragma unroll
        for (int q = 0; q < 4; q++) acc[n][q] = 0.f;

    // ---- fused slice-streamed GEMM (R12-proven loop body) ------------------
#pragma unroll 1
    for (int c = 0; c < 10; c++) {
        // consume slice c: 48 HMMA (3-pass bf16 split, bh cached)
        {
            const int ar0 = (m0 + g) * 8 + t;
            const int ar1 = (m0 + g + 8) * 8 + t;
            uint32_t ah0 = SLH32[ar0], ah1 = SLH32[ar1];
            uint32_t ah2 = SLH32[ar0 + 4], ah3 = SLH32[ar1 + 4];
            uint32_t al0 = SLL32[ar0], al1 = SLL32[ar1];
            uint32_t al2 = SLL32[ar0 + 4], al3 = SLL32[ar1 + 4];

            uint32_t bh[16][2];
#pragma unroll
            for (int n = 0; n < 16; n++) {
                const int br = (8 * n + g) * 84 + 8 * c + t;
                bh[n][0] = BH32[br];
                bh[n][1] = BH32[br + 4];
                hmma_bf16(acc[n], ah0, ah1, ah2, ah3, bh[n][0], bh[n][1]);
            }
#pragma unroll
            for (int n = 0; n < 16; n++) {
                const int br = (8 * n + g) * 84 + 8 * c + t;
                uint32_t bl0 = BL32[br], bl1 = BL32[br + 4];
                hmma_bf16(acc[n], ah0, ah1, ah2, ah3, bl0, bl1);
            }
#pragma unroll
            for (int n = 0; n < 16; n++)
                hmma_bf16(acc[n], al0, al1, al2, al3, bh[n][0], bh[n][1]);
        }
        if (c == 9) break;
        __syncthreads();  // all reads of slice c done

        // build slice c+1
        if (c < 8) {
            const int k = c;
            const float* mk = mu + (b * 128 + k * 16 + 8 * h) * HW + hw0 + p;
            float v[8];
#pragma unroll
            for (int j = 0; j < 8; j++) v[j] = mk[j * HW];
            float dk = 0.f;
#pragma unroll
            for (int j = 0; j < 8; j++) {
                float d = shX[(8 * h + j) * 128 + p] - v[j];
                dk = fmaf(d, d, dk);
            }
            atomicAdd(&shAL[k * 128 + p], dk);  // 2 adds: fp-commutative
            uint4 hi, lo;
            pack8(v, hi, lo);
            *(uint4*)((char*)SLH32 + p * 32 + h * 16) = hi;
            *(uint4*)((char*)SLL32 + p * 32 + h * 16) = lo;
        } else {
            // c == 8: finalize dens/alpha/rho, build rho slice (chunk 9)
            if (h == 0) {
                float rho[8];
#pragma unroll
                for (int k = 0; k < 8; k++) {
                    float dist = shAL[k * 128 + p];
                    float sg = sigma[(b * 8 + k) * HW + hw0 + p];
                    float pv = pi_in[(b * 8 + k) * HW + hw0 + p];
                    float s2 = sg * sg;
                    float tt = 6.283185307179586f * s2;
                    float t2 = tt * tt, t4 = t2 * t2;
                    float dens = __expf(-dist / (2.f * s2)) / (t4 * t4);
                    float a = pv * dens;
                    shAL[k * 128 + p] = a;  // alpha overwrites dist
                    rho[k] = a * dens;
                }
                uint4 hi, lo;
                pack8(rho, hi, lo);
                *(uint4*)((char*)SLH32 + p * 32) = hi;
                *(uint4*)((char*)SLL32 + p * 32) = lo;
            } else {
                *(uint4*)((char*)SLH32 + p * 32 + 16) = make_uint4(0, 0, 0, 0);
                *(uint4*)((char*)SLL32 + p * 32 + 16) = make_uint4(0, 0, 0, 0);
            }
        }
        __syncthreads();  // slice c+1 ready
    }
    __syncthreads();  // all B reads done before mn overwrite

    // ---- scatter acc -> mn tile (B region dead) ---------------------------
#pragma unroll
    for (int n = 0; n < 16; n++) {
        const int nc = 8 * n + 2 * t;
        mn[nc * MN_STRIDE + m0 + g] = acc[n][0];
        mn[(nc + 1) * MN_STRIDE + m0 + g] = acc[n][1];
        mn[nc * MN_STRIDE + m0 + g + 8] = acc[n][2];
        mn[(nc + 1) * MN_STRIDE + m0 + g + 8] = acc[n][3];
    }
    __syncthreads();

    // ---- finalize: 256 threads, warp-halves split the 128 outputs ---------
    {
        const int hh = w >> 2;                   // output half
        const int pp = ((w & 3) << 5) | l;       // pixel 0..127
        const int ob = hh * 64;

        float sj[8];
#pragma unroll
        for (int j = 0; j < 8; j++) sj[j] = hh ? 0.f : shMISC[8 + j];
        float d2l[4] = {0.f, 0.f, 0.f, 0.f};
        float* outMuBase = out + OFF_MU + (b * 128 + ob) * HW + hw0 + pp;
#pragma unroll 4
        for (int oo = 0; oo < 64; oo++) {
            const int o = ob + oo;
            float v = mn[o * MN_STRIDE + pp] + shBMU[o];
            v = fmaxf(v, 0.f);
            outMuBase[oo * HW] = v;
            float4 wsa = *(const float4*)(shS + (16 + o) * 8);
            float4 wsb = *(const float4*)(shS + (16 + o) * 8 + 4);
            sj[0] = fmaf(wsa.x, v, sj[0]);
            sj[1] = fmaf(wsa.y, v, sj[1]);
            sj[2] = fmaf(wsa.z, v, sj[2]);
            sj[3] = fmaf(wsa.w, v, sj[3]);
            sj[4] = fmaf(wsb.x, v, sj[4]);
            sj[5] = fmaf(wsb.y, v, sj[5]);
            sj[6] = fmaf(wsb.z, v, sj[6]);
            sj[7] = fmaf(wsb.w, v, sj[7]);
            float d = shX[(o & 15) * 128 + pp] - v;
            d2l[oo >> 4] = fmaf(d, d, d2l[oo >> 4]);
        }
        if (hh) {
#pragma unroll
            for (int j = 0; j < 8; j++) spare[pp * 16 + j] = sj[j];
#pragma unroll
            for (int i = 0; i < 4; i++) spare[pp * 16 + 8 + i] = d2l[i];
        }
        __syncthreads();
        if (!hh) {
            float d2[8];
#pragma unroll
            for (int j = 0; j < 8; j++) sj[j] += spare[pp * 16 + j];
#pragma unroll
            for (int i = 0; i < 4; i++) {
                d2[i] = d2l[i];
                d2[4 + i] = spare[pp * 16 + 8 + i];
            }
            // rho from chunk-9 slice (hi+lo bf16)
            float rho[8];
            {
                const __nv_bfloat16* rh =
                    (const __nv_bfloat16*)((char*)SLH32 + pp * 32);
                const __nv_bfloat16* rl =
                    (const __nv_bfloat16*)((char*)SLL32 + pp * 32);
#pragma unroll
                for (int r = 0; r < 8; r++)
                    rho[r] = __bfloat162float(rh[r]) + __bfloat162float(rl[r]);
            }
            // softmax -> pi_new
            float piv[8], al[8], z[8], pin[8];
#pragma unroll
            for (int k = 0; k < 8; k++) {
                piv[k] = pi_in[(b * 8 + k) * HW + hw0 + pp];
                al[k] = shAL[k * 128 + pp];
            }
            float zmax = -1e30f;
#pragma unroll
            for (int j = 0; j < 8; j++) {
                float zj = shMISC[j];
#pragma unroll
                for (int i = 0; i < 8; i++) {
                    zj = fmaf(shWPI[j * 16 + i], piv[i], zj);
                    zj = fmaf(shWPI[j * 16 + 8 + i], al[i], zj);
                }
                z[j] = zj;
                zmax = fmaxf(zmax, zj);
            }
            float s = 0.f;
#pragma unroll
            for (int j = 0; j < 8; j++) {
                z[j] = __expf(z[j] - zmax);
                s += z[j];
            }
            float inv = 1.0f / s;
#pragma unroll
            for (int j = 0; j < 8; j++) {
                pin[j] = z[j] * inv;
                out[OFF_PI + (b * 8 + j) * HW + hw0 + pp] = pin[j];
            }
            // x and rho channels of sigma matvec
#pragma unroll 4
            for (int c = 0; c < 16; c++) {
                float xv = shX[c * 128 + pp];
#pragma unroll
                for (int j = 0; j < 8; j++)
                    sj[j] = fmaf(shS[c * 8 + j], xv, sj[j]);
            }
#pragma unroll
            for (int r = 0; r < 8; r++) {
#pragma unroll
                for (int j = 0; j < 8; j++)
                    sj[j] = fmaf(shS[(144 + r) * 8 + j], rho[r], sj[j]);
            }
            float gg = shMISC[24];
#pragma unroll
            for (int j = 0; j < 8; j++) {
                float sn = __expf(fmaxf(sj[j], 0.f));
                out[OFF_SIG + (b * 8 + j) * HW + hw0 + pp] = sn;
                float s2 = sn * sn;
                float tt = 6.283185307179586f * s2;
                float t2 = tt * tt, t4 = t2 * t2;
                float dens2 = __expf(-d2[j] / (2.f * s2)) / (t4 * t4);
                gg = fmaf(shMISC[16 + j], pin[j] * dens2, gg);
            }
            out[OFF_G + b * HW + hw0 + pp] = 1.0f / (1.0f + __expf(-gg));
        }
    }
}

extern "C" void kernel_launch(void* const* d_in, const int* in_sizes, int n_in,
                              void* d_out, int out_size) {
    (void)in_sizes;
    (void)n_in;
    (void)out_size;
    const float* x = (const float*)d_in[0];
    const float* pi = (const float*)d_in[1];
    const float* mu = (const float*)d_in[2];
    const float* sigma = (const float*)d_in[3];
    const float* Wpi = (const float*)d_in[4];
    const float* bpi = (const float*)d_in[5];
    const float* Wmu = (const float*)d_in[6];
    const float* bmu = (const float*)d_in[7];
    const float* Wsig = (const float*)d_in[8];
    const float* bsig = (const float*)d_in[9];
    const float* Wg = (const float*)d_in[10];
    const float* bg = (const float*)d_in[11];
    float* out = (float*)d_out;

    prep_B_kernel<<<(128 * KPAD + 255) / 256, 256>>>(Wmu);

    cudaFuncSetAttribute(gmm_block_kernel,
                         cudaFuncAttributeMaxDynamicSharedMemorySize,
                         SMEM_BYTES);
    gmm_block_kernel<<<2048, 256, SMEM_BYTES>>>(x, pi, mu, sigma, Wpi, bpi,
                                                Wmu, bmu, Wsig, bsig, Wg, bg,
                                                out);
}

// round 15
// speedup vs baseline: 1.4182x; 1.0690x over previous
#include <cuda_runtime.h>
#include <cuda_bf16.h>
#include <cstdint>

#define HW 16384
#define OFF_PI 0
#define OFF_MU 2097152
#define OFF_SIG 35651584
#define OFF_G 37748736

// smem byte offsets (total 108416 -> 2 CTAs/SM)
#define SMB_B 0         // B fragments 81920 ; reused as mn tile post-GEMM
#define SMB_SLH 81920   // A-slice hi bf16 [128 px][16 ch] = 4096
#define SMB_SLL 86016   // A-slice lo bf16                 = 4096
#define SMB_X 90112     // x fp32 [16][128]                = 8192
#define SMB_AL 98304    // dist accum -> alpha [8][128]    = 4096
#define SMB_S 102400    // Wsig^T fp32 [152][8]            = 4864
#define SMB_BMU 107264  // 128 f
#define SMB_WPI 107776  // 128 f
#define SMB_MISC 108288 // bpi[0..7] bsig[8..15] Wg[16..23] bg[24]
#define SMEM_BYTES 108416

#define MN_STRIDE 132      // fp32 mu_new tile [128 out][132], in SMB_B
#define SMB_SPARE 67584    // sj/d2 partials [128 px][16 f], in SMB_B region

typedef unsigned long long ull;

// B fragments: [chunk c 0..9][n 0..15][lane 0..31] of uint4
// {bh0, bh1, bl0, bl1} for mma row o=8n+(l>>2), k-words t=(l&3) and t+4.
__device__ __align__(16) uint4 g_B[5120];

extern "C" __global__ void prep_B_kernel(const float* __restrict__ Wmu) {
    int i = blockIdx.x * 256 + threadIdx.x;
    if (i >= 5120) return;
    int c = i >> 9;            // 0..9
    int n = (i >> 5) & 15;     // 0..15
    int l = i & 31;
    int g = l >> 2, t = l & 3;
    int o = 8 * n + g;
    float v[4];
    int ch[4] = {16 * c + 2 * t, 16 * c + 2 * t + 1, 16 * c + 8 + 2 * t,
                 16 * c + 8 + 2 * t + 1};
#pragma unroll
    for (int q = 0; q < 4; q++)
        v[q] = (ch[q] < 152) ? Wmu[o * 152 + ch[q]] : 0.f;
    __nv_bfloat162 h0 = __floats2bfloat162_rn(v[0], v[1]);
    __nv_bfloat162 h1 = __floats2bfloat162_rn(v[2], v[3]);
    float2 f0 = __bfloat1622float2(h0);
    float2 f1 = __bfloat1622float2(h1);
    __nv_bfloat162 l0 = __floats2bfloat162_rn(v[0] - f0.x, v[1] - f0.y);
    __nv_bfloat162 l1 = __floats2bfloat162_rn(v[2] - f1.x, v[3] - f1.y);
    uint4 frag;
    frag.x = *(uint32_t*)&h0;
    frag.y = *(uint32_t*)&h1;
    frag.z = *(uint32_t*)&l0;
    frag.w = *(uint32_t*)&l1;
    g_B[i] = frag;
}

__device__ __forceinline__ void hmma_bf16(float* d, uint32_t a0, uint32_t a1,
                                          uint32_t a2, uint32_t a3,
                                          uint32_t b0, uint32_t b1) {
    asm volatile(
        "mma.sync.aligned.m16n8k16.row.col.f32.bf16.bf16.f32 "
        "{%0,%1,%2,%3}, {%4,%5,%6,%7}, {%8,%9}, {%0,%1,%2,%3};"
        : "+f"(d[0]), "+f"(d[1]), "+f"(d[2]), "+f"(d[3])
        : "r"(a0), "r"(a1), "r"(a2), "r"(a3), "r"(b0), "r"(b1));
}

// pack 8 consecutive-channel fp32 -> 4 bf16x2 hi words + 4 lo words
__device__ __forceinline__ void pack8(const float* v, uint4& hi, uint4& lo) {
    uint32_t h[4], l[4];
#pragma unroll
    for (int i = 0; i < 4; i++) {
        float a = v[2 * i], c = v[2 * i + 1];
        __nv_bfloat162 h2 = __floats2bfloat162_rn(a, c);
        float2 hf = __bfloat1622float2(h2);
        __nv_bfloat162 l2 = __floats2bfloat162_rn(a - hf.x, c - hf.y);
        h[i] = *(uint32_t*)&h2;
        l[i] = *(uint32_t*)&l2;
    }
    hi = make_uint4(h[0], h[1], h[2], h[3]);
    lo = make_uint4(l[0], l[1], l[2], l[3]);
}

extern "C" __global__ void __launch_bounds__(256, 2)
gmm_block_kernel(const float* __restrict__ x, const float* __restrict__ pi_in,
                 const float* __restrict__ mu, const float* __restrict__ sigma,
                 const float* __restrict__ Wpi, const float* __restrict__ bpi,
                 const float* __restrict__ Wmu, const float* __restrict__ bmu,
                 const float* __restrict__ Wsig, const float* __restrict__ bsig,
                 const float* __restrict__ Wg, const float* __restrict__ bg,
                 float* __restrict__ out) {
    extern __shared__ char sm[];
    float* shX = (float*)(sm + SMB_X);
    float* shAL = (float*)(sm + SMB_AL);
    float* shS = (float*)(sm + SMB_S);
    float* shBMU = (float*)(sm + SMB_BMU);
    float* shWPI = (float*)(sm + SMB_WPI);
    float* shMISC = (float*)(sm + SMB_MISC);
    uint32_t* SLH32 = (uint32_t*)(sm + SMB_SLH);
    uint32_t* SLL32 = (uint32_t*)(sm + SMB_SLL);
    const uint4* BF = (const uint4*)(sm + SMB_B);
    float* mn = (float*)(sm + SMB_B);             // after GEMM (B dead)
    float* spare = (float*)(sm + SMB_B + SMB_SPARE);

    const int tid = threadIdx.x;
    const int blk = blockIdx.x;  // 2048 CTAs x 128 pixels
    const int b = blk >> 7;
    const int hw0 = (blk & 127) << 7;

    // ---- stage 1: cp.async B (80KB, L2-hot) + stage small operands --------
    {
        uint32_t dst = (uint32_t)__cvta_generic_to_shared(sm + SMB_B);
        const char* src = (const char*)&g_B[0];
#pragma unroll 1
        for (int i = tid * 16; i < 81920; i += 256 * 16) {
            asm volatile("cp.async.cg.shared.global [%0], [%1], 16;" ::"r"(
                             dst + i),
                         "l"(src + i)
                         : "memory");
        }
        asm volatile("cp.async.commit_group;" ::: "memory");
    }
    for (int i = tid; i < 1216; i += 256) {  // Wsig[j][c] -> shS[c][j]
        int j = i / 152, c = i - j * 152;
        shS[c * 8 + j] = Wsig[i];
    }
    for (int i = tid; i < 2048; i += 256) {
        int c = i >> 7, p = i & 127;
        shX[i] = x[(b * 16 + c) * HW + hw0 + p];
    }
    if (tid < 128) {
        shBMU[tid] = bmu[tid];
        shWPI[tid] = Wpi[tid];
    } else if (tid < 136) {
        int k = tid - 128;
        shMISC[k] = bpi[k];
        shMISC[8 + k] = bsig[k];
        shMISC[16 + k] = Wg[k];
    }
    if (tid == 255) shMISC[24] = bg[0];
    for (int i = tid; i < 1024; i += 256) shAL[i] = 0.f;  // dist accum
    __syncthreads();  // shX staged (cp.async for B still in flight)

    const int w = tid >> 5, l = tid & 31;
    const int g = l >> 2, t = l & 3;
    const int m0 = 16 * w;
    const int p = tid & 127, h = tid >> 7;  // slice-builder role

    // ---- build slice 0 (x channels) while B streams in --------------------
    {
        float v0[8];
#pragma unroll
        for (int j = 0; j < 8; j++) v0[j] = shX[(8 * h + j) * 128 + p];
        uint4 hi, lo;
        pack8(v0, hi, lo);
        *(uint4*)((char*)SLH32 + p * 32 + h * 16) = hi;
        *(uint4*)((char*)SLL32 + p * 32 + h * 16) = lo;
    }
    asm volatile("cp.async.wait_group 0;" ::: "memory");
    __syncthreads();  // slice 0 + B visible

    float acc[16][4];
#pragma unroll
    for (int n = 0; n < 16; n++)
#pragma unroll
        for (int q = 0; q < 4; q++) acc[n][q] = 0.f;

    // ---- fused slice-streamed GEMM ----------------------------------------
#pragma unroll 1
    for (int c = 0; c < 10; c++) {
        // L2-prefetch next chunk's mu (64 lines) -- no destination register
        if (c < 8 && tid < 64) {
            const float* pf =
                mu + (b * 128 + c * 16 + (tid >> 2)) * HW + hw0 + (tid & 3) * 32;
            asm volatile("prefetch.global.L2 [%0];" ::"l"(pf));
        }

        // consume slice c: 48 HMMA (3-pass bf16 split, fragment LDS.128)
        {
            const int ar0 = (m0 + g) * 8 + t;
            const int ar1 = (m0 + g + 8) * 8 + t;
            uint32_t ah0 = SLH32[ar0], ah1 = SLH32[ar1];
            uint32_t ah2 = SLH32[ar0 + 4], ah3 = SLH32[ar1 + 4];
            uint32_t al0 = SLL32[ar0], al1 = SLL32[ar1];
            uint32_t al2 = SLL32[ar0 + 4], al3 = SLL32[ar1 + 4];
            const uint4* bf = BF + c * 512 + l;
#pragma unroll
            for (int n = 0; n < 16; n++) {
                uint4 f = bf[n * 32];
                hmma_bf16(acc[n], ah0, ah1, ah2, ah3, f.x, f.y);
                hmma_bf16(acc[n], ah0, ah1, ah2, ah3, f.z, f.w);
                hmma_bf16(acc[n], al0, al1, al2, al3, f.x, f.y);
            }
        }
        if (c == 9) break;
        __syncthreads();  // all reads of slice c done

        // build slice c+1
        if (c < 8) {
            const int k = c;
            const float* mk = mu + (b * 128 + k * 16 + 8 * h) * HW + hw0 + p;
            float v[8];
#pragma unroll
            for (int j = 0; j < 8; j++) v[j] = mk[j * HW];
            float dk = 0.f;
#pragma unroll
            for (int j = 0; j < 8; j++) {
                float d = shX[(8 * h + j) * 128 + p] - v[j];
                dk = fmaf(d, d, dk);
            }
            atomicAdd(&shAL[k * 128 + p], dk);  // 2 adds: fp-commutative
            uint4 hi, lo;
            pack8(v, hi, lo);
            *(uint4*)((char*)SLH32 + p * 32 + h * 16) = hi;
            *(uint4*)((char*)SLL32 + p * 32 + h * 16) = lo;
        } else {
            // c == 8: finalize dens/alpha/rho, build rho slice (chunk 9)
            if (h == 0) {
                float rho[8];
#pragma unroll
                for (int k = 0; k < 8; k++) {
                    float dist = shAL[k * 128 + p];
                    float sg = sigma[(b * 8 + k) * HW + hw0 + p];
                    float pv = pi_in[(b * 8 + k) * HW + hw0 + p];
                    float s2 = sg * sg;
                    float tt = 6.283185307179586f * s2;
                    float t2 = tt * tt, t4 = t2 * t2;
                    float dens = __expf(-dist / (2.f * s2)) / (t4 * t4);
                    float a = pv * dens;
                    shAL[k * 128 + p] = a;  // alpha overwrites dist
                    rho[k] = a * dens;
                }
                uint4 hi, lo;
                pack8(rho, hi, lo);
                *(uint4*)((char*)SLH32 + p * 32) = hi;
                *(uint4*)((char*)SLL32 + p * 32) = lo;
            } else {
                *(uint4*)((char*)SLH32 + p * 32 + 16) = make_uint4(0, 0, 0, 0);
                *(uint4*)((char*)SLL32 + p * 32 + 16) = make_uint4(0, 0, 0, 0);
            }
        }
        __syncthreads();  // slice c+1 ready
    }
    __syncthreads();  // all B reads done before mn overwrite

    // ---- scatter acc -> mn tile (B region dead) ---------------------------
#pragma unroll
    for (int n = 0; n < 16; n++) {
        const int nc = 8 * n + 2 * t;
        mn[nc * MN_STRIDE + m0 + g] = acc[n][0];
        mn[(nc + 1) * MN_STRIDE + m0 + g] = acc[n][1];
        mn[nc * MN_STRIDE + m0 + g + 8] = acc[n][2];
        mn[(nc + 1) * MN_STRIDE + m0 + g + 8] = acc[n][3];
    }
    __syncthreads();

    // ---- finalize: 256 threads, warp-halves split the 128 outputs ---------
    {
        const int hh = w >> 2;                   // output half
        const int pp = ((w & 3) << 5) | l;       // pixel 0..127
        const int ob = hh * 64;

        float sj[8];
#pragma unroll
        for (int j = 0; j < 8; j++) sj[j] = hh ? 0.f : shMISC[8 + j];
        float d2l[4] = {0.f, 0.f, 0.f, 0.f};
        float* outMuBase = out + OFF_MU + (b * 128 + ob) * HW + hw0 + pp;
#pragma unroll 4
        for (int oo = 0; oo < 64; oo++) {
            const int o = ob + oo;
            float v = mn[o * MN_STRIDE + pp] + shBMU[o];
            v = fmaxf(v, 0.f);
            outMuBase[oo * HW] = v;
            float4 wsa = *(const float4*)(shS + (16 + o) * 8);
            float4 wsb = *(const float4*)(shS + (16 + o) * 8 + 4);
            sj[0] = fmaf(wsa.x, v, sj[0]);
            sj[1] = fmaf(wsa.y, v, sj[1]);
            sj[2] = fmaf(wsa.z, v, sj[2]);
            sj[3] = fmaf(wsa.w, v, sj[3]);
            sj[4] = fmaf(wsb.x, v, sj[4]);
            sj[5] = fmaf(wsb.y, v, sj[5]);
            sj[6] = fmaf(wsb.z, v, sj[6]);
            sj[7] = fmaf(wsb.w, v, sj[7]);
            float d = shX[(o & 15) * 128 + pp] - v;
            d2l[oo >> 4] = fmaf(d, d, d2l[oo >> 4]);
        }
        if (hh) {
#pragma unroll
            for (int j = 0; j < 8; j++) spare[pp * 16 + j] = sj[j];
#pragma unroll
            for (int i = 0; i < 4; i++) spare[pp * 16 + 8 + i] = d2l[i];
        }
        __syncthreads();
        if (!hh) {
            float d2[8];
#pragma unroll
            for (int j = 0; j < 8; j++) sj[j] += spare[pp * 16 + j];
#pragma unroll
            for (int i = 0; i < 4; i++) {
                d2[i] = d2l[i];
                d2[4 + i] = spare[pp * 16 + 8 + i];
            }
            // rho from chunk-9 slice (hi+lo bf16)
            float rho[8];
            {
                const __nv_bfloat16* rh =
                    (const __nv_bfloat16*)((char*)SLH32 + pp * 32);
                const __nv_bfloat16* rl =
                    (const __nv_bfloat16*)((char*)SLL32 + pp * 32);
#pragma unroll
                for (int r = 0; r < 8; r++)
                    rho[r] = __bfloat162float(rh[r]) + __bfloat162float(rl[r]);
            }
            // softmax -> pi_new
            float piv[8], al[8], z[8], pin[8];
#pragma unroll
            for (int k = 0; k < 8; k++) {
                piv[k] = pi_in[(b * 8 + k) * HW + hw0 + pp];
                al[k] = shAL[k * 128 + pp];
            }
            float zmax = -1e30f;
#pragma unroll
            for (int j = 0; j < 8; j++) {
                float zj = shMISC[j];
#pragma unroll
                for (int i = 0; i < 8; i++) {
                    zj = fmaf(shWPI[j * 16 + i], piv[i], zj);
                    zj = fmaf(shWPI[j * 16 + 8 + i], al[i], zj);
                }
                z[j] = zj;
                zmax = fmaxf(zmax, zj);
            }
            float s = 0.f;
#pragma unroll
            for (int j = 0; j < 8; j++) {
                z[j] = __expf(z[j] - zmax);
                s += z[j];
            }
            float inv = 1.0f / s;
#pragma unroll
            for (int j = 0; j < 8; j++) {
                pin[j] = z[j] * inv;
                out[OFF_PI + (b * 8 + j) * HW + hw0 + pp] = pin[j];
            }
            // x and rho channels of sigma matvec
#pragma unroll 4
            for (int c = 0; c < 16; c++) {
                float xv = shX[c * 128 + pp];
#pragma unroll
                for (int j = 0; j < 8; j++)
                    sj[j] = fmaf(shS[c * 8 + j], xv, sj[j]);
            }
#pragma unroll
            for (int r = 0; r < 8; r++) {
#pragma unroll
                for (int j = 0; j < 8; j++)
                    sj[j] = fmaf(shS[(144 + r) * 8 + j], rho[r], sj[j]);
            }
            float gg = shMISC[24];
#pragma unroll
            for (int j = 0; j < 8; j++) {
                float sn = __expf(fmaxf(sj[j], 0.f));
                out[OFF_SIG + (b * 8 + j) * HW + hw0 + pp] = sn;
                float s2 = sn * sn;
                float tt = 6.283185307179586f * s2;
                float t2 = tt * tt, t4 = t2 * t2;
                float dens2 = __expf(-d2[j] / (2.f * s2)) / (t4 * t4);
                gg = fmaf(shMISC[16 + j], pin[j] * dens2, gg);
            }
            out[OFF_G + b * HW + hw0 + pp] = 1.0f / (1.0f + __expf(-gg));
        }
    }
}

extern "C" void kernel_launch(void* const* d_in, const int* in_sizes, int n_in,
                              void* d_out, int out_size) {
    (void)in_sizes;
    (void)n_in;
    (void)out_size;
    const float* x = (const float*)d_in[0];
    const float* pi = (const float*)d_in[1];
    const float* mu = (const float*)d_in[2];
    const float* sigma = (const float*)d_in[3];
    const float* Wpi = (const float*)d_in[4];
    const float* bpi = (const float*)d_in[5];
    const float* Wmu = (const float*)d_in[6];
    const float* bmu = (const float*)d_in[7];
    const float* Wsig = (const float*)d_in[8];
    const float* bsig = (const float*)d_in[9];
    const float* Wg = (const float*)d_in[10];
    const float* bg = (const float*)d_in[11];
    float* out = (float*)d_out;

    prep_B_kernel<<<20, 256>>>(Wmu);

    cudaFuncSetAttribute(gmm_block_kernel,
                         cudaFuncAttributeMaxDynamicSharedMemorySize,
                         SMEM_BYTES);
    gmm_block_kernel<<<2048, 256, SMEM_BYTES>>>(x, pi, mu, sigma, Wpi, bpi,
                                                Wmu, bmu, Wsig, bsig, Wg, bg,
                                                out);
}

// round 16
// speedup vs baseline: 1.4749x; 1.0400x over previous
#include <cuda_runtime.h>
#include <cuda_bf16.h>
#include <cstdint>

#define HW 16384
#define OFF_PI 0
#define OFF_MU 2097152
#define OFF_SIG 35651584
#define OFF_G 37748736

// smem byte offsets (total 108416 -> 2 CTAs/SM)
#define SMB_B 0         // B fragments 81920 ; staging/mn reuse dead sub-regions
#define SMB_SLH 81920   // A-slice hi bf16 [128 px][16 ch] = 4096
#define SMB_SLL 86016   // A-slice lo bf16                 = 4096
#define SMB_X 90112     // x fp32 [16][128]                = 8192
#define SMB_AL 98304    // dist accum -> alpha [8][128]    = 4096
#define SMB_S 102400    // Wsig^T fp32 [152][8]            = 4864
#define SMB_BMU 107264  // 128 f
#define SMB_WPI 107776  // 128 f
#define SMB_MISC 108288 // bpi[0..7] bsig[8..15] Wg[16..23] bg[24]
#define SMEM_BYTES 108416

#define MN_STRIDE 132      // fp32 mu_new tile [128 out][132], in SMB_B
#define SMB_SPARE 67584    // sj/d2 partials [128 px][16 f], in SMB_B region

typedef unsigned long long ull;

// B fragments: [chunk c 0..9][n 0..15][lane 0..31] of uint4
// {bh0, bh1, bl0, bl1} for mma row o=8n+(l>>2), k-words t=(l&3) and t+4.
__device__ __align__(16) uint4 g_B[5120];

extern "C" __global__ void prep_B_kernel(const float* __restrict__ Wmu) {
    int i = blockIdx.x * 256 + threadIdx.x;
    if (i >= 5120) return;
    int c = i >> 9;            // 0..9
    int n = (i >> 5) & 15;     // 0..15
    int l = i & 31;
    int g = l >> 2, t = l & 3;
    int o = 8 * n + g;
    float v[4];
    int ch[4] = {16 * c + 2 * t, 16 * c + 2 * t + 1, 16 * c + 8 + 2 * t,
                 16 * c + 8 + 2 * t + 1};
#pragma unroll
    for (int q = 0; q < 4; q++)
        v[q] = (ch[q] < 152) ? Wmu[o * 152 + ch[q]] : 0.f;
    __nv_bfloat162 h0 = __floats2bfloat162_rn(v[0], v[1]);
    __nv_bfloat162 h1 = __floats2bfloat162_rn(v[2], v[3]);
    float2 f0 = __bfloat1622float2(h0);
    float2 f1 = __bfloat1622float2(h1);
    __nv_bfloat162 l0 = __floats2bfloat162_rn(v[0] - f0.x, v[1] - f0.y);
    __nv_bfloat162 l1 = __floats2bfloat162_rn(v[2] - f1.x, v[3] - f1.y);
    uint4 frag;
    frag.x = *(uint32_t*)&h0;
    frag.y = *(uint32_t*)&h1;
    frag.z = *(uint32_t*)&l0;
    frag.w = *(uint32_t*)&l1;
    g_B[i] = frag;
}

__device__ __forceinline__ void hmma_bf16(float* d, uint32_t a0, uint32_t a1,
                                          uint32_t a2, uint32_t a3,
                                          uint32_t b0, uint32_t b1) {
    asm volatile(
        "mma.sync.aligned.m16n8k16.row.col.f32.bf16.bf16.f32 "
        "{%0,%1,%2,%3}, {%4,%5,%6,%7}, {%8,%9}, {%0,%1,%2,%3};"
        : "+f"(d[0]), "+f"(d[1]), "+f"(d[2]), "+f"(d[3])
        : "r"(a0), "r"(a1), "r"(a2), "r"(a3), "r"(b0), "r"(b1));
}

// pack 8 consecutive-channel fp32 -> 4 bf16x2 hi words + 4 lo words
__device__ __forceinline__ void pack8(const float* v, uint4& hi, uint4& lo) {
    uint32_t h[4], l[4];
#pragma unroll
    for (int i = 0; i < 4; i++) {
        float a = v[2 * i], c = v[2 * i + 1];
        __nv_bfloat162 h2 = __floats2bfloat162_rn(a, c);
        float2 hf = __bfloat1622float2(h2);
        __nv_bfloat162 l2 = __floats2bfloat162_rn(a - hf.x, c - hf.y);
        h[i] = *(uint32_t*)&h2;
        l[i] = *(uint32_t*)&l2;
    }
    hi = make_uint4(h[0], h[1], h[2], h[3]);
    lo = make_uint4(l[0], l[1], l[2], l[3]);
}

extern "C" __global__ void __launch_bounds__(256, 2)
gmm_block_kernel(const float* __restrict__ x, const float* __restrict__ pi_in,
                 const float* __restrict__ mu, const float* __restrict__ sigma,
                 const float* __restrict__ Wpi, const float* __restrict__ bpi,
                 const float* __restrict__ Wmu, const float* __restrict__ bmu,
                 const float* __restrict__ Wsig, const float* __restrict__ bsig,
                 const float* __restrict__ Wg, const float* __restrict__ bg,
                 float* __restrict__ out) {
    extern __shared__ char sm[];
    float* shX = (float*)(sm + SMB_X);
    float* shAL = (float*)(sm + SMB_AL);
    float* shS = (float*)(sm + SMB_S);
    float* shBMU = (float*)(sm + SMB_BMU);
    float* shWPI = (float*)(sm + SMB_WPI);
    float* shMISC = (float*)(sm + SMB_MISC);
    uint32_t* SLH32 = (uint32_t*)(sm + SMB_SLH);
    uint32_t* SLL32 = (uint32_t*)(sm + SMB_SLL);
    const uint4* BF = (const uint4*)(sm + SMB_B);
    float* mn = (float*)(sm + SMB_B);             // after GEMM (B dead)
    float* spare = (float*)(sm + SMB_B + SMB_SPARE);

    const int tid = threadIdx.x;
    const int blk = blockIdx.x;  // 2048 CTAs x 128 pixels
    const int b = blk >> 7;
    const int hw0 = (blk & 127) << 7;

    // ---- stage 1: cp.async B (80KB, L2-hot) + stage small operands --------
    {
        uint32_t dst = (uint32_t)__cvta_generic_to_shared(sm + SMB_B);
        const char* src = (const char*)&g_B[0];
#pragma unroll 1
        for (int i = tid * 16; i < 81920; i += 256 * 16) {
            asm volatile("cp.async.cg.shared.global [%0], [%1], 16;" ::"r"(
                             dst + i),
                         "l"(src + i)
                         : "memory");
        }
        asm volatile("cp.async.commit_group;" ::: "memory");
    }
    for (int i = tid; i < 1216; i += 256) {  // Wsig[j][c] -> shS[c][j]
        int j = i / 152, c = i - j * 152;
        shS[c * 8 + j] = Wsig[i];
    }
    for (int i = tid; i < 2048; i += 256) {
        int c = i >> 7, p = i & 127;
        shX[i] = x[(b * 16 + c) * HW + hw0 + p];
    }
    if (tid < 128) {
        shBMU[tid] = bmu[tid];
        shWPI[tid] = Wpi[tid];
    } else if (tid < 136) {
        int k = tid - 128;
        shMISC[k] = bpi[k];
        shMISC[8 + k] = bsig[k];
        shMISC[16 + k] = Wg[k];
    }
    if (tid == 255) shMISC[24] = bg[0];
    for (int i = tid; i < 1024; i += 256) shAL[i] = 0.f;  // dist accum
    __syncthreads();  // shX staged (cp.async for B still in flight)

    const int w = tid >> 5, l = tid & 31;
    const int g = l >> 2, t = l & 3;
    const int m0 = 16 * w;
    const int p = tid & 127, h = tid >> 7;  // slice-builder role

    // ---- build slice 0 (x channels) while B streams in --------------------
    {
        float v0[8];
#pragma unroll
        for (int j = 0; j < 8; j++) v0[j] = shX[(8 * h + j) * 128 + p];
        uint4 hi, lo;
        pack8(v0, hi, lo);
        *(uint4*)((char*)SLH32 + p * 32 + h * 16) = hi;
        *(uint4*)((char*)SLL32 + p * 32 + h * 16) = lo;
    }
    asm volatile("cp.async.wait_group 0;" ::: "memory");
    __syncthreads();  // slice 0 + B visible

    float acc[16][4];
#pragma unroll
    for (int n = 0; n < 16; n++)
#pragma unroll
        for (int q = 0; q < 4; q++) acc[n][q] = 0.f;

    // staging: mu chunk k (k>=2) parked in dead B-frag region B[k-2] (8KB),
    // cp.async issued at top of iter k-1, consumed by the build at end of
    // iter k. Chunks k=0,1 use direct LDG + L2 prefetch (no dead region yet).
    // Thread handles two 16B granules per staged chunk.
    const int s_ch0 = tid >> 5;             // granule tid: ch = tid/32
    const int s_px0 = (tid & 31) * 4;       // 4 floats
    const int s_ch1 = (tid + 256) >> 5;
    const int s_px1 = (tid & 31) * 4;

    // ---- fused slice-streamed GEMM ----------------------------------------
#pragma unroll 1
    for (int c = 0; c < 10; c++) {
        // issue staging for mu k=c+1 into B[c-1]  (valid for k=c+1 in [2,7])
        if (c >= 1 && c <= 6) {
            const int k = c + 1;
            uint32_t dstb = (uint32_t)__cvta_generic_to_shared(
                sm + SMB_B + (ull)(k - 2) * 8192);
            const float* srcb = mu + (b * 128 + k * 16) * HW + hw0;
            asm volatile("cp.async.cg.shared.global [%0], [%1], 16;" ::"r"(
                             dstb + (uint32_t)(s_ch0 * 512 + s_px0 * 4)),
                         "l"(srcb + s_ch0 * HW + s_px0)
                         : "memory");
            asm volatile("cp.async.cg.shared.global [%0], [%1], 16;" ::"r"(
                             dstb + (uint32_t)(s_ch1 * 512 + s_px1 * 4)),
                         "l"(srcb + s_ch1 * HW + s_px1)
                         : "memory");
            asm volatile("cp.async.commit_group;" ::: "memory");
        }
        // L2 prefetch for the two LDG-built chunks (k=0 at c=0, k=1 at c=1)
        if (c < 2 && tid < 64) {
            const float* pf =
                mu + (b * 128 + c * 16 + (tid >> 2)) * HW + hw0 + (tid & 3) * 32;
            asm volatile("prefetch.global.L2 [%0];" ::"l"(pf));
        }

        // consume slice c: 48 HMMA (3-pass bf16 split, fragment LDS.128)
        {
            const int ar0 = (m0 + g) * 8 + t;
            const int ar1 = (m0 + g + 8) * 8 + t;
            uint32_t ah0 = SLH32[ar0], ah1 = SLH32[ar1];
            uint32_t ah2 = SLH32[ar0 + 4], ah3 = SLH32[ar1 + 4];
            uint32_t al0 = SLL32[ar0], al1 = SLL32[ar1];
            uint32_t al2 = SLL32[ar0 + 4], al3 = SLL32[ar1 + 4];
            const uint4* bf = BF + c * 512 + l;
#pragma unroll
            for (int n = 0; n < 16; n++) {
                uint4 f = bf[n * 32];
                hmma_bf16(acc[n], ah0, ah1, ah2, ah3, f.x, f.y);
                hmma_bf16(acc[n], ah0, ah1, ah2, ah3, f.z, f.w);
                hmma_bf16(acc[n], al0, al1, al2, al3, f.x, f.y);
            }
        }
        if (c == 9) break;
        __syncthreads();  // all reads of slice c done

        // build slice c+1 (mu k=c)
        if (c < 8) {
            const int k = c;
            float v[8];
            if (k >= 2) {
                // staged: wait for k's group (one newer may be in flight)
                if (k == 7)
                    asm volatile("cp.async.wait_group 0;" ::: "memory");
                else
                    asm volatile("cp.async.wait_group 1;" ::: "memory");
                const float* st = (const float*)(sm + SMB_B + (ull)(k - 2) * 8192);
#pragma unroll
                for (int j = 0; j < 8; j++) v[j] = st[(8 * h + j) * 128 + p];
            } else {
                const float* mk =
                    mu + (b * 128 + k * 16 + 8 * h) * HW + hw0 + p;
#pragma unroll
                for (int j = 0; j < 8; j++) v[j] = mk[j * HW];
            }
            float dk = 0.f;
#pragma unroll
            for (int j = 0; j < 8; j++) {
                float d = shX[(8 * h + j) * 128 + p] - v[j];
                dk = fmaf(d, d, dk);
            }
            atomicAdd(&shAL[k * 128 + p], dk);  // 2 adds: fp-commutative
            uint4 hi, lo;
            pack8(v, hi, lo);
            *(uint4*)((char*)SLH32 + p * 32 + h * 16) = hi;
            *(uint4*)((char*)SLL32 + p * 32 + h * 16) = lo;
        } else {
            // c == 8: finalize dens/alpha/rho, build rho slice (chunk 9)
            if (h == 0) {
                float rho[8];
#pragma unroll
                for (int k = 0; k < 8; k++) {
                    float dist = shAL[k * 128 + p];
                    float sg = sigma[(b * 8 + k) * HW + hw0 + p];
                    float pv = pi_in[(b * 8 + k) * HW + hw0 + p];
                    float s2 = sg * sg;
                    float tt = 6.283185307179586f * s2;
                    float t2 = tt * tt, t4 = t2 * t2;
                    float dens = __expf(-dist / (2.f * s2)) / (t4 * t4);
                    float a = pv * dens;
                    shAL[k * 128 + p] = a;  // alpha overwrites dist
                    rho[k] = a * dens;
                }
                uint4 hi, lo;
                pack8(rho, hi, lo);
                *(uint4*)((char*)SLH32 + p * 32) = hi;
                *(uint4*)((char*)SLL32 + p * 32) = lo;
            } else {
                *(uint4*)((char*)SLH32 + p * 32 + 16) = make_uint4(0, 0, 0, 0);
                *(uint4*)((char*)SLL32 + p * 32 + 16) = make_uint4(0, 0, 0, 0);
            }
        }
        __syncthreads();  // slice c+1 ready
    }
    __syncthreads();  // all B reads done before mn overwrite

    // ---- scatter acc -> mn tile (B region dead) ---------------------------
#pragma unroll
    for (int n = 0; n < 16; n++) {
        const int nc = 8 * n + 2 * t;
        mn[nc * MN_STRIDE + m0 + g] = acc[n][0];
        mn[(nc + 1) * MN_STRIDE + m0 + g] = acc[n][1];
        mn[nc * MN_STRIDE + m0 + g + 8] = acc[n][2];
        mn[(nc + 1) * MN_STRIDE + m0 + g + 8] = acc[n][3];
    }
    __syncthreads();

    // ---- finalize: 256 threads, warp-halves split the 128 outputs ---------
    {
        const int hh = w >> 2;                   // output half
        const int pp = ((w & 3) << 5) | l;       // pixel 0..127
        const int ob = hh * 64;

        float sj[8];
#pragma unroll
        for (int j = 0; j < 8; j++) sj[j] = hh ? 0.f : shMISC[8 + j];
        float d2l[4] = {0.f, 0.f, 0.f, 0.f};
        float* outMuBase = out + OFF_MU + (b * 128 + ob) * HW + hw0 + pp;
#pragma unroll 4
        for (int oo = 0; oo < 64; oo++) {
            const int o = ob + oo;
            float v = mn[o * MN_STRIDE + pp] + shBMU[o];
            v = fmaxf(v, 0.f);
            outMuBase[oo * HW] = v;
            float4 wsa = *(const float4*)(shS + (16 + o) * 8);
            float4 wsb = *(const float4*)(shS + (16 + o) * 8 + 4);
            sj[0] = fmaf(wsa.x, v, sj[0]);
            sj[1] = fmaf(wsa.y, v, sj[1]);
            sj[2] = fmaf(wsa.z, v, sj[2]);
            sj[3] = fmaf(wsa.w, v, sj[3]);
            sj[4] = fmaf(wsb.x, v, sj[4]);
            sj[5] = fmaf(wsb.y, v, sj[5]);
            sj[6] = fmaf(wsb.z, v, sj[6]);
            sj[7] = fmaf(wsb.w, v, sj[7]);
            float d = shX[(o & 15) * 128 + pp] - v;
            d2l[oo >> 4] = fmaf(d, d, d2l[oo >> 4]);
        }
        if (hh) {
#pragma unroll
            for (int j = 0; j < 8; j++) spare[pp * 16 + j] = sj[j];
#pragma unroll
            for (int i = 0; i < 4; i++) spare[pp * 16 + 8 + i] = d2l[i];
        }
        __syncthreads();
        if (!hh) {
            float d2[8];
#pragma unroll
            for (int j = 0; j < 8; j++) sj[j] += spare[pp * 16 + j];
#pragma unroll
            for (int i = 0; i < 4; i++) {
                d2[i] = d2l[i];
                d2[4 + i] = spare[pp * 16 + 8 + i];
            }
            // rho from chunk-9 slice (hi+lo bf16)
            float rho[8];
            {
                const __nv_bfloat16* rh =
                    (const __nv_bfloat16*)((char*)SLH32 + pp * 32);
                const __nv_bfloat16* rl =
                    (const __nv_bfloat16*)((char*)SLL32 + pp * 32);
#pragma unroll
                for (int r = 0; r < 8; r++)
                    rho[r] = __bfloat162float(rh[r]) + __bfloat162float(rl[r]);
            }
            // softmax -> pi_new
            float piv[8], al[8], z[8], pin[8];
#pragma unroll
            for (int k = 0; k < 8; k++) {
                piv[k] = pi_in[(b * 8 + k) * HW + hw0 + pp];
                al[k] = shAL[k * 128 + pp];
            }
            float zmax = -1e30f;
#pragma unroll
            for (int j = 0; j < 8; j++) {
                float zj = shMISC[j];
#pragma unroll
                for (int i = 0; i < 8; i++) {
                    zj = fmaf(shWPI[j * 16 + i], piv[i], zj);
                    zj = fmaf(shWPI[j * 16 + 8 + i], al[i], zj);
                }
                z[j] = zj;
                zmax = fmaxf(zmax, zj);
            }
            float s = 0.f;
#pragma unroll
            for (int j = 0; j < 8; j++) {
                z[j] = __expf(z[j] - zmax);
                s += z[j];
            }
            float inv = 1.0f / s;
#pragma unroll
            for (int j = 0; j < 8; j++) {
                pin[j] = z[j] * inv;
                out[OFF_PI + (b * 8 + j) * HW + hw0 + pp] = pin[j];
            }
            // x and rho channels of sigma matvec
#pragma unroll 4
            for (int c = 0; c < 16; c++) {
                float xv = shX[c * 128 + pp];
#pragma unroll
                for (int j = 0; j < 8; j++)
                    sj[j] = fmaf(shS[c * 8 + j], xv, sj[j]);
            }
#pragma unroll
            for (int r = 0; r < 8; r++) {
#pragma unroll
                for (int j = 0; j < 8; j++)
                    sj[j] = fmaf(shS[(144 + r) * 8 + j], rho[r], sj[j]);
            }
            float gg = shMISC[24];
#pragma unroll
            for (int j = 0; j < 8; j++) {
                float sn = __expf(fmaxf(sj[j], 0.f));
                out[OFF_SIG + (b * 8 + j) * HW + hw0 + pp] = sn;
                float s2 = sn * sn;
                float tt = 6.283185307179586f * s2;
                float t2 = tt * tt, t4 = t2 * t2;
                float dens2 = __expf(-d2[j] / (2.f * s2)) / (t4 * t4);
                gg = fmaf(shMISC[16 + j], pin[j] * dens2, gg);
            }
            out[OFF_G + b * HW + hw0 + pp] = 1.0f / (1.0f + __expf(-gg));
        }
    }
}

extern "C" void kernel_launch(void* const* d_in, const int* in_sizes, int n_in,
                              void* d_out, int out_size) {
    (void)in_sizes;
    (void)n_in;
    (void)out_size;
    const float* x = (const float*)d_in[0];
    const float* pi = (const float*)d_in[1];
    const float* mu = (const float*)d_in[2];
    const float* sigma = (const float*)d_in[3];
    const float* Wpi = (const float*)d_in[4];
    const float* bpi = (const float*)d_in[5];
    const float* Wmu = (const float*)d_in[6];
    const float* bmu = (const float*)d_in[7];
    const float* Wsig = (const float*)d_in[8];
    const float* bsig = (const float*)d_in[9];
    const float* Wg = (const float*)d_in[10];
    const float* bg = (const float*)d_in[11];
    float* out = (float*)d_out;

    prep_B_kernel<<<20, 256>>>(Wmu);

    cudaFuncSetAttribute(gmm_block_kernel,
                         cudaFuncAttributeMaxDynamicSharedMemorySize,
                         SMEM_BYTES);
    gmm_block_kernel<<<2048, 256, SMEM_BYTES>>>(x, pi, mu, sigma, Wpi, bpi,
                                                Wmu, bmu, Wsig, bsig, Wg, bg,
                                                out);
}